// round 9
// baseline (speedup 1.0000x reference)
#include <cuda_runtime.h>
#include <cuda_bf16.h>
#include <cstdint>

// ===========================================================================
// HyperConvS tf32: x NHWC tf32 convert (ch-interleaved) -> weight-gen ->
// implicit GEMM conv (mma.sync.m16n8k8.tf32). CTA 128px x 128oc, 256 thr,
// 8 warps of 32x64, 48 stages of (16-ch chunk, dy). 82.9KB smem -> 2 CTA/SM.
// ===========================================================================

#define HH 64
#define WW 64
#define CC 256
#define OCC 256

__device__ float g_x[32 * 64 * 64 * 256];   // NHWC, tf32-rounded, ch-interleaved
__device__ float g_w[9 * 256 * 256];        // [tap][oc][ic-interleaved], tf32

// ---- helpers ----
__device__ __forceinline__ uint32_t smem_u32(const void* p) {
    uint32_t a;
    asm("{ .reg .u64 t; cvta.to.shared.u64 t, %1; cvt.u32.u64 %0, t; }"
        : "=r"(a) : "l"(p));
    return a;
}
__device__ __forceinline__ void cp_async16(uint32_t dst, const void* src, uint32_t nbytes) {
    asm volatile("cp.async.cg.shared.global [%0], [%1], 16, %2;"
                 :: "r"(dst), "l"(src), "r"(nbytes) : "memory");
}
__device__ __forceinline__ void cp_commit() {
    asm volatile("cp.async.commit_group;" ::: "memory");
}
template <int N>
__device__ __forceinline__ void cp_wait() {
    asm volatile("cp.async.wait_group %0;" :: "n"(N) : "memory");
}
__device__ __forceinline__ void lds128(uint32_t* r, uint32_t addr) {
    asm volatile("ld.shared.v4.b32 {%0,%1,%2,%3}, [%4];"
                 : "=r"(r[0]), "=r"(r[1]), "=r"(r[2]), "=r"(r[3]) : "r"(addr));
}
__device__ __forceinline__ void mma_tf32(float* c, uint32_t a0, uint32_t a1,
                                         uint32_t a2, uint32_t a3,
                                         uint32_t b0, uint32_t b1) {
    asm volatile(
        "mma.sync.aligned.m16n8k8.row.col.f32.tf32.tf32.f32 "
        "{%0,%1,%2,%3}, {%4,%5,%6,%7}, {%8,%9}, {%0,%1,%2,%3};"
        : "+f"(c[0]), "+f"(c[1]), "+f"(c[2]), "+f"(c[3])
        : "r"(a0), "r"(a1), "r"(a2), "r"(a3), "r"(b0), "r"(b1));
}
__device__ __forceinline__ uint32_t f2tf32(float v) {
    uint32_t o;
    asm("cvt.rna.tf32.f32 %0, %1;" : "=r"(o) : "f"(v));
    return o;
}

// ---------------------------------------------------------------------------
// Kernel: weight generation -> tf32 g_w[tap][oc][ic-interleaved].
// ---------------------------------------------------------------------------
__global__ __launch_bounds__(256)
void weight_gen_kernel(const float* __restrict__ z,
                       const float* __restrict__ W1,
                       const float* __restrict__ B1,
                       const float* __restrict__ W2,
                       const float* __restrict__ B2) {
    __shared__ float w1t[64 * 65];     // [n][d]
    __shared__ float w2t[64 * 149];    // [d][k]
    __shared__ float z_s[16 * 64];
    __shared__ float a_s[16 * 64];
    const int b  = blockIdx.x;
    const int lg = blockIdx.y;
    const int t  = threadIdx.x;
    const int bpos = ((b & 3) << 2) | (b >> 2);   // interleaved position

    for (int i = t; i < 64 * 64; i += 256) {
        const int d = i >> 6, n = i & 63;
        w1t[n * 65 + d] = W1[(b * 64 + d) * 64 + n];
    }
    for (int i = t; i < 144 * 64; i += 256) {
        const int k = i >> 6, d = i & 63;
        w2t[d * 149 + k] = W2[(b * 144 + k) * 64 + d];
    }
    for (int i = t; i < 1024; i += 256) z_s[i] = z[lg * 16 * 64 + i];
    __syncthreads();

    for (int i = t; i < 1024; i += 256) {
        const int il = i >> 6, d = i & 63;
        float s = B1[b * 64 + d];
        #pragma unroll 16
        for (int n = 0; n < 64; ++n) s += w1t[n * 65 + d] * z_s[il * 64 + n];
        a_s[i] = s;
    }
    __syncthreads();

    for (int i = t; i < 2304; i += 256) {
        const int il = i / 144, k = i - il * 144;
        float s = B2[b * 144 + k];
        #pragma unroll 16
        for (int d = 0; d < 64; ++d) s += w2t[d * 149 + k] * a_s[il * 64 + d];
        const int b2 = k / 9;
        const int tap = k - b2 * 9;
        const int o = lg * 16 + b2;
        const int icpos = il * 16 + bpos;
        g_w[(tap * 256 + o) * 256 + icpos] = __uint_as_float(f2tf32(s));
    }
}

// ---------------------------------------------------------------------------
// Kernel: NCHW fp32 -> NHWC tf32, channel-interleaved.
// ---------------------------------------------------------------------------
__global__ __launch_bounds__(256)
void x_convert_kernel(const float* __restrict__ x) {
    __shared__ float tile[8][32][36];
    const int y  = blockIdx.x;
    const int n  = blockIdx.y;
    const int px0 = blockIdx.z * 32;
    const int t  = threadIdx.x;
    const int w  = t >> 5;
    const int lane = t & 31;
    const int c0 = w * 32;

    #pragma unroll
    for (int cg = 0; cg < 8; ++cg) {
        const int cl = cg * 4 + (lane >> 3);
        const int pl = (lane & 7) * 4;
        float4 v = *(const float4*)(x +
            (((size_t)(n * CC + c0 + cl) * HH + y) * WW) + px0 + pl);
        *(float4*)&tile[w][cl][pl] = v;
    }
    __syncwarp();

    #pragma unroll
    for (int it = 0; it < 8; ++it) {
        const int pl = it * 4 + (lane >> 3);
        const int h = lane & 7;
        const int blk = h >> 2;
        const int q = h & 3;
        uint32_t vv[4];
        #pragma unroll
        for (int i = 0; i < 4; ++i)
            vv[i] = f2tf32(tile[w][blk * 16 + q + 4 * i][pl]);
        float* dst = g_x + ((size_t)(n * HH + y) * WW + px0 + pl) * 256
                   + c0 + blk * 16 + q * 4;
        *(uint4*)dst = make_uint4(vv[0], vv[1], vv[2], vv[3]);
    }
}

// ---------------------------------------------------------------------------
// Kernel: implicit-GEMM conv, tf32, 2 CTAs/SM.
// CTA: 128 px (2 rows x 64 cols) x 128 oc, 256 threads, 8 warps of 32x64
// (warp_m = wid&3, warp_n = wid>>2). Stage s (0..47): chunk = s/3 (16 ch),
// dy = s%3 - 1. A: [2 buf][264 halo rows][64 B]; B: [2 buf][3 dx][128][64 B].
// Natural conflict-free layout (64B rows, 2-row = 128B period): no swizzle.
// ---------------------------------------------------------------------------
#define A_BUF_SZ 16896u                // 264 * 64
#define A_REGION (2 * A_BUF_SZ)       // 33792
#define B_TILE  8192u                 // 128 oc * 64 B (per dx)
#define B_STAGE (3 * B_TILE)          // 24576
#define B_OFF   A_REGION
#define SMEM_DYN (A_REGION + 2 * B_STAGE)   // 82944

struct Ctx {
    uint32_t sbase;
    int n, y0, oc0;
};

__device__ __forceinline__ void issue_A(const Ctx& c, int chunk, int t) {
    const int c0 = chunk * 16;
    const uint32_t bufo = (chunk & 1) ? A_BUF_SZ : 0u;
    #pragma unroll
    for (int it = 0; it < 5; ++it) {
        const int idx = t + it * 256;              // 0..1055
        if (idx >= 1056) break;
        const int r = idx >> 2;                    // halo row 0..263
        const int cl = idx & 3;                    // 16B chunk
        const int hrow = r / 66;
        const int hcol = r - hrow * 66;
        const int gy = c.y0 - 1 + hrow;
        const int gx = hcol - 1;
        const bool valid = ((unsigned)gy < 64u) && ((unsigned)gx < 64u);
        const float* src = valid
            ? g_x + (((size_t)(c.n * HH + gy) * WW + gx) * 256 + c0 + cl * 4)
            : g_x;
        cp_async16(c.sbase + bufo + (uint32_t)r * 64 + (uint32_t)cl * 16,
                   src, valid ? 16u : 0u);
    }
}

__device__ __forceinline__ void issue_B(const Ctx& c, int s, int t) {
    const int chunk = s / 3;
    const int tr = s - chunk * 3;
    const uint32_t bufo = (uint32_t)(s & 1) * B_STAGE;
    #pragma unroll
    for (int it = 0; it < 6; ++it) {
        const int idx = t + it * 256;              // 0..1535
        const int cl = idx & 3;
        const int oc = (idx >> 2) & 127;
        const int dxi = idx >> 9;
        const int tap = tr * 3 + dxi;
        const float* src = g_w +
            ((size_t)(tap * 256 + c.oc0 + oc) * 256 + chunk * 16 + cl * 4);
        cp_async16(c.sbase + B_OFF + bufo + (uint32_t)dxi * B_TILE
                   + (uint32_t)oc * 64 + (uint32_t)cl * 16, src, 16u);
    }
}

__global__ __launch_bounds__(256, 2)
void conv_mma_kernel(float* __restrict__ out) {
    extern __shared__ char dsm[];
    const uint32_t sbase = smem_u32(dsm);

    const int t = threadIdx.x;
    const int lane = t & 31;
    const int wid = t >> 5;
    const int warp_m = wid & 3;        // 32-px slot within 128
    const int warp_n = wid >> 2;       // oc half
    const int y0 = blockIdx.x * 2;
    const int n = blockIdx.y;
    const int oc0 = blockIdx.z * 128;

    Ctx ctx; ctx.sbase = sbase; ctx.n = n; ctx.y0 = y0; ctx.oc0 = oc0;

    float acc[2][8][4];
    #pragma unroll
    for (int mi = 0; mi < 2; ++mi)
        #pragma unroll
        for (int ni = 0; ni < 8; ++ni)
            #pragma unroll
            for (int k = 0; k < 4; ++k) acc[mi][ni][k] = 0.f;

    const int frow = lane >> 2;        // 0..7
    const int fcol = lane & 3;         // 0..3

    // per-mi pixel-block coordinates (within 128-px tile)
    int mrl[2], mxc[2];
    #pragma unroll
    for (int mi = 0; mi < 2; ++mi) {
        const int p0 = warp_m * 32 + mi * 16;
        mrl[mi] = p0 >> 6;             // image row 0/1
        mxc[mi] = p0 & 63;             // col base
    }

    issue_A(ctx, 0, t);
    issue_B(ctx, 0, t);
    cp_commit();

    for (int s = 0; s < 48; ++s) {
        if ((s % 3) == 1) cp_wait<1>(); else cp_wait<0>();
        __syncthreads();

        // prefetch: B(s+1) as its own group, then A(chunk+1) as its own group
        if (s + 1 < 48) { issue_B(ctx, s + 1, t); cp_commit(); }
        if ((s % 3) == 0 && (s / 3) + 1 < 16) { issue_A(ctx, s / 3 + 1, t); cp_commit(); }

        const int chunk = s / 3;
        const int dy = (s - chunk * 3) - 1;
        const uint32_t abase = sbase + ((chunk & 1) ? A_BUF_SZ : 0u);
        const uint32_t bstage = sbase + B_OFF + (uint32_t)(s & 1) * B_STAGE;

        #pragma unroll
        for (int dxi = 0; dxi < 3; ++dxi) {
            const int dx = dxi - 1;
            const uint32_t btile = bstage + (uint32_t)dxi * B_TILE;

            uint32_t a[2][2][4];       // [mi][px +0 / +8][4] = k16
            #pragma unroll
            for (int mi = 0; mi < 2; ++mi) {
                const uint32_t r = (uint32_t)((mrl[mi] + 1 + dy) * 66
                                   + mxc[mi] + 1 + dx + frow);
                const uint32_t ad = abase + r * 64 + (uint32_t)fcol * 16;
                lds128(a[mi][0], ad);
                lds128(a[mi][1], ad + 512);        // +8 pixels
            }
            #pragma unroll
            for (int h = 0; h < 2; ++h) {          // B in two quads (reg limit)
                uint32_t bb[4][4];
                #pragma unroll
                for (int j = 0; j < 4; ++j) {
                    const uint32_t row = (uint32_t)(warp_n * 64 + (h * 4 + j) * 8 + frow);
                    lds128(bb[j], btile + row * 64 + (uint32_t)fcol * 16);
                }
                #pragma unroll
                for (int mi = 0; mi < 2; ++mi) {
                    #pragma unroll
                    for (int j = 0; j < 4; ++j) {
                        float* cacc = acc[mi][h * 4 + j];
                        mma_tf32(cacc, a[mi][0][0], a[mi][1][0],
                                       a[mi][0][1], a[mi][1][1],
                                       bb[j][0], bb[j][1]);
                        mma_tf32(cacc, a[mi][0][2], a[mi][1][2],
                                       a[mi][0][3], a[mi][1][3],
                                       bb[j][2], bb[j][3]);
                    }
                }
            }
        }
    }

    // ---- epilogue: two 64-oc halves through smem, coalesced float4 stores
    float* sC = (float*)dsm;                 // [64 oc][132 px]
    const int r0 = lane >> 2;
    const int col0 = (lane & 3) * 2;
    #pragma unroll
    for (int h = 0; h < 2; ++h) {
        __syncthreads();
        if (warp_n == h) {
            #pragma unroll
            for (int mi = 0; mi < 2; ++mi) {
                #pragma unroll
                for (int ni = 0; ni < 8; ++ni) {
                    const int px = warp_m * 32 + mi * 16 + r0;
                    const int oc = ni * 8 + col0;            // local 0..63
                    sC[oc * 132 + px]           = acc[mi][ni][0];
                    sC[(oc + 1) * 132 + px]     = acc[mi][ni][1];
                    sC[oc * 132 + px + 8]       = acc[mi][ni][2];
                    sC[(oc + 1) * 132 + px + 8] = acc[mi][ni][3];
                }
            }
        }
        __syncthreads();
        #pragma unroll
        for (int it = 0; it < 8; ++it) {
            const int linear = t + it * 256;     // 0..2047 float4
            const int oc = linear >> 5;          // 32 float4 per oc
            const int q = linear & 31;
            float4 v = *(const float4*)&sC[oc * 132 + q * 4];
            const int yy = y0 + (q >> 4);
            const int xx = (q & 15) * 4;
            *(float4*)&out[((size_t)(n * OCC + oc0 + h * 64 + oc) * HH + yy) * WW + xx] = v;
        }
    }
}

// ---------------------------------------------------------------------------
extern "C" void kernel_launch(void* const* d_in, const int* in_sizes, int n_in,
                              void* d_out, int out_size) {
    const float* x  = (const float*)d_in[0];
    const float* z  = (const float*)d_in[1];
    const float* W1 = (const float*)d_in[2];
    const float* B1 = (const float*)d_in[3];
    const float* W2 = (const float*)d_in[4];
    const float* B2 = (const float*)d_in[5];
    float* out = (float*)d_out;

    x_convert_kernel<<<dim3(64, 32, 2), 256>>>(x);

    weight_gen_kernel<<<dim3(16, 16), 256>>>(z, W1, B1, W2, B2);

    cudaFuncSetAttribute(conv_mma_kernel,
                         cudaFuncAttributeMaxDynamicSharedMemorySize, SMEM_DYN);
    conv_mma_kernel<<<dim3(32, 32, 2), 256, SMEM_DYN>>>(out);
}

// round 10
// speedup vs baseline: 1.1240x; 1.1240x over previous
#include <cuda_runtime.h>
#include <cuda_bf16.h>
#include <cstdint>

// ===========================================================================
// HyperConvS tf32: x NHWC tf32 convert (ch-interleaved) -> weight-gen ->
// implicit GEMM conv (mma.sync.m16n8k8.tf32). CTA 256px x 128oc, 256 thr,
// 8 warps of 64x64, 24 stages of (32ch, dy). SMSP warp pairs are phase-
// staggered by 3 of 6 (dx,k16) blocks to keep the HMMA pipe fed during
// LDS bursts.
// ===========================================================================

#define HH 64
#define WW 64
#define CC 256
#define OCC 256

__device__ float g_x[32 * 64 * 64 * 256];   // NHWC, tf32-rounded, ch-interleaved
__device__ float g_w[9 * 256 * 256];        // [tap][oc][ic-interleaved], tf32

// ---- helpers ----
__device__ __forceinline__ uint32_t smem_u32(const void* p) {
    uint32_t a;
    asm("{ .reg .u64 t; cvta.to.shared.u64 t, %1; cvt.u32.u64 %0, t; }"
        : "=r"(a) : "l"(p));
    return a;
}
__device__ __forceinline__ void cp_async16(uint32_t dst, const void* src, uint32_t nbytes) {
    asm volatile("cp.async.cg.shared.global [%0], [%1], 16, %2;"
                 :: "r"(dst), "l"(src), "r"(nbytes) : "memory");
}
__device__ __forceinline__ void cp_commit() {
    asm volatile("cp.async.commit_group;" ::: "memory");
}
template <int N>
__device__ __forceinline__ void cp_wait() {
    asm volatile("cp.async.wait_group %0;" :: "n"(N) : "memory");
}
__device__ __forceinline__ void lds128(uint32_t* r, uint32_t addr) {
    asm volatile("ld.shared.v4.b32 {%0,%1,%2,%3}, [%4];"
                 : "=r"(r[0]), "=r"(r[1]), "=r"(r[2]), "=r"(r[3]) : "r"(addr));
}
__device__ __forceinline__ void mma_tf32(float* c, uint32_t a0, uint32_t a1,
                                         uint32_t a2, uint32_t a3,
                                         uint32_t b0, uint32_t b1) {
    asm volatile(
        "mma.sync.aligned.m16n8k8.row.col.f32.tf32.tf32.f32 "
        "{%0,%1,%2,%3}, {%4,%5,%6,%7}, {%8,%9}, {%0,%1,%2,%3};"
        : "+f"(c[0]), "+f"(c[1]), "+f"(c[2]), "+f"(c[3])
        : "r"(a0), "r"(a1), "r"(a2), "r"(a3), "r"(b0), "r"(b1));
}
__device__ __forceinline__ uint32_t f2tf32(float v) {
    uint32_t o;
    asm("cvt.rna.tf32.f32 %0, %1;" : "=r"(o) : "f"(v));
    return o;
}

// ---------------------------------------------------------------------------
// Kernel: weight generation -> tf32 g_w[tap][oc][ic-interleaved].
// ILP-jammed: layer1 4 concurrent accumulators, layer2 3.
// ---------------------------------------------------------------------------
__global__ __launch_bounds__(256)
void weight_gen_kernel(const float* __restrict__ z,
                       const float* __restrict__ W1,
                       const float* __restrict__ B1,
                       const float* __restrict__ W2,
                       const float* __restrict__ B2) {
    __shared__ float w1t[64 * 65];     // [n][d]
    __shared__ float w2t[64 * 149];    // [d][k]
    __shared__ float z_s[16 * 64];
    __shared__ float a_s[16 * 64];
    const int b  = blockIdx.x;
    const int lg = blockIdx.y;
    const int t  = threadIdx.x;
    const int bpos = ((b & 3) << 2) | (b >> 2);   // interleaved position

    for (int i = t; i < 64 * 64; i += 256) {
        const int d = i >> 6, n = i & 63;
        w1t[n * 65 + d] = W1[(b * 64 + d) * 64 + n];
    }
    for (int i = t; i < 144 * 64; i += 256) {
        const int k = i >> 6, d = i & 63;
        w2t[d * 149 + k] = W2[(b * 144 + k) * 64 + d];
    }
    for (int i = t; i < 1024; i += 256) z_s[i] = z[lg * 16 * 64 + i];
    __syncthreads();

    // layer 1: 4 outputs per thread, jammed (shared w1t load)
    {
        const int d = t & 63;
        const int il0 = t >> 6;                 // 0..3
        const float bias = B1[b * 64 + d];
        float s0 = bias, s1 = bias, s2 = bias, s3 = bias;
        #pragma unroll 8
        for (int n = 0; n < 64; ++n) {
            const float w = w1t[n * 65 + d];
            s0 += w * z_s[(il0 + 0) * 64 + n];
            s1 += w * z_s[(il0 + 4) * 64 + n];
            s2 += w * z_s[(il0 + 8) * 64 + n];
            s3 += w * z_s[(il0 + 12) * 64 + n];
        }
        a_s[(il0 + 0) * 64 + d] = s0;
        a_s[(il0 + 4) * 64 + d] = s1;
        a_s[(il0 + 8) * 64 + d] = s2;
        a_s[(il0 + 12) * 64 + d] = s3;
    }
    __syncthreads();

    // layer 2 + scatter: 9 outputs per thread, jammed 3-wide
    #pragma unroll
    for (int j = 0; j < 3; ++j) {
        const int ia = t + j * 768;
        const int ib = ia + 256;
        const int ic2 = ia + 512;
        const int ila = ia / 144, ka = ia - ila * 144;
        const int ilb = ib / 144, kb = ib - ilb * 144;
        const int ilc = ic2 / 144, kc = ic2 - ilc * 144;
        float sa = B2[b * 144 + ka];
        float sb = B2[b * 144 + kb];
        float sc = B2[b * 144 + kc];
        #pragma unroll 8
        for (int d = 0; d < 64; ++d) {
            sa += w2t[d * 149 + ka] * a_s[ila * 64 + d];
            sb += w2t[d * 149 + kb] * a_s[ilb * 64 + d];
            sc += w2t[d * 149 + kc] * a_s[ilc * 64 + d];
        }
        {
            const int b2 = ka / 9, tap = ka - b2 * 9;
            g_w[(tap * 256 + lg * 16 + b2) * 256 + ila * 16 + bpos] =
                __uint_as_float(f2tf32(sa));
        }
        {
            const int b2 = kb / 9, tap = kb - b2 * 9;
            g_w[(tap * 256 + lg * 16 + b2) * 256 + ilb * 16 + bpos] =
                __uint_as_float(f2tf32(sb));
        }
        {
            const int b2 = kc / 9, tap = kc - b2 * 9;
            g_w[(tap * 256 + lg * 16 + b2) * 256 + ilc * 16 + bpos] =
                __uint_as_float(f2tf32(sc));
        }
    }
}

// ---------------------------------------------------------------------------
// Kernel: NCHW fp32 -> NHWC tf32, channel-interleaved.
// ---------------------------------------------------------------------------
__global__ __launch_bounds__(256)
void x_convert_kernel(const float* __restrict__ x) {
    __shared__ float tile[8][32][36];
    const int y  = blockIdx.x;
    const int n  = blockIdx.y;
    const int px0 = blockIdx.z * 32;
    const int t  = threadIdx.x;
    const int w  = t >> 5;
    const int lane = t & 31;
    const int c0 = w * 32;

    #pragma unroll
    for (int cg = 0; cg < 8; ++cg) {
        const int cl = cg * 4 + (lane >> 3);
        const int pl = (lane & 7) * 4;
        float4 v = *(const float4*)(x +
            (((size_t)(n * CC + c0 + cl) * HH + y) * WW) + px0 + pl);
        *(float4*)&tile[w][cl][pl] = v;
    }
    __syncwarp();

    #pragma unroll
    for (int it = 0; it < 8; ++it) {
        const int pl = it * 4 + (lane >> 3);
        const int h = lane & 7;
        const int blk = h >> 2;
        const int q = h & 3;
        uint32_t vv[4];
        #pragma unroll
        for (int i = 0; i < 4; ++i)
            vv[i] = f2tf32(tile[w][blk * 16 + q + 4 * i][pl]);
        float* dst = g_x + ((size_t)(n * HH + y) * WW + px0 + pl) * 256
                   + c0 + blk * 16 + q * 4;
        *(uint4*)dst = make_uint4(vv[0], vv[1], vv[2], vv[3]);
    }
}

// ---------------------------------------------------------------------------
// Kernel: implicit-GEMM conv, tf32, 8 warps of 64x64 (R8 structure).
// Stage s (0..23): chunk = s/3 (32 ch), dy = s%3 - 1.
// Stage body = 6 blocks (dxi = blk>>1, k16 = blk&1); warps 4-7 traverse the
// blocks rotated by 3 so each SMSP's warp pair is anti-phased (one loads
// while the other MMAs).
// A: [2 buf][396 halo rows][128 B]; B: [2 buf][3 dx][128 oc][128 B].
// ---------------------------------------------------------------------------
#define A_BUF_SZ 50688u                // 396 * 128
#define A_REGION (2 * A_BUF_SZ)       // 101376
#define B_TILE  16384u                // 128 oc * 128 B (per dx)
#define B_STAGE (3 * B_TILE)          // 49152
#define B_OFF   A_REGION
#define SMEM_DYN (A_REGION + 2 * B_STAGE)   // 199680

struct Ctx {
    uint32_t sbase;
    int n, y0, oc0;
};

__device__ __forceinline__ void issue_A(const Ctx& c, int chunk, int t) {
    const int c0 = chunk * 32;
    const uint32_t bufo = (chunk & 1) ? A_BUF_SZ : 0u;
    #pragma unroll
    for (int it = 0; it < 13; ++it) {
        const int idx = t + it * 256;              // 0..3167
        if (idx >= 3168) break;
        const int r = idx >> 3;                    // halo row 0..395
        const int cl = idx & 7;                    // logical 16B chunk
        const int hrow = r / 66;
        const int hcol = r - hrow * 66;
        const int gy = c.y0 - 1 + hrow;
        const int gx = hcol - 1;
        const bool valid = ((unsigned)gy < 64u) && ((unsigned)gx < 64u);
        const float* src = valid
            ? g_x + (((size_t)(c.n * HH + gy) * WW + gx) * 256 + c0 + cl * 4)
            : g_x;
        const uint32_t pcl = (uint32_t)(cl ^ ((r & 1) << 2));
        cp_async16(c.sbase + bufo + (uint32_t)r * 128 + pcl * 16,
                   src, valid ? 16u : 0u);
    }
}

__device__ __forceinline__ void issue_B(const Ctx& c, int s, int t) {
    const int chunk = s / 3;
    const int tr = s - chunk * 3;
    const uint32_t bufo = (uint32_t)(s & 1) * B_STAGE;
    #pragma unroll
    for (int it = 0; it < 12; ++it) {
        const int idx = t + it * 256;              // 0..3071
        const int cl = idx & 7;
        const int oc = (idx >> 3) & 127;
        const int dxi = idx >> 10;
        const int tap = tr * 3 + dxi;
        const float* src = g_w +
            ((size_t)(tap * 256 + c.oc0 + oc) * 256 + chunk * 32 + cl * 4);
        const uint32_t pcl = (uint32_t)(cl ^ ((oc & 1) << 2));
        cp_async16(c.sbase + B_OFF + bufo + (uint32_t)dxi * B_TILE
                   + (uint32_t)oc * 128 + pcl * 16, src, 16u);
    }
}

__global__ __launch_bounds__(256, 1)
void conv_mma_kernel(float* __restrict__ out) {
    extern __shared__ char dsm[];
    const uint32_t sbase = smem_u32(dsm);

    const int t = threadIdx.x;
    const int lane = t & 31;
    const int wid = t >> 5;
    const int warp_m = wid & 3;        // image row within CTA tile
    const int warp_n = wid >> 2;       // oc half
    const int y0 = blockIdx.x * 4;
    const int n = blockIdx.y;
    const int oc0 = blockIdx.z * 128;

    Ctx ctx; ctx.sbase = sbase; ctx.n = n; ctx.y0 = y0; ctx.oc0 = oc0;

    float acc[4][8][4];
    #pragma unroll
    for (int mi = 0; mi < 4; ++mi)
        #pragma unroll
        for (int ni = 0; ni < 8; ++ni)
            #pragma unroll
            for (int k = 0; k < 4; ++k) acc[mi][ni][k] = 0.f;

    const int frow = lane >> 2;        // 0..7
    const int fcol = lane & 3;         // 0..3
    const int phase = ((wid >> 2) & 1) * 3;   // anti-phase the SMSP warp pair

    issue_A(ctx, 0, t);
    issue_B(ctx, 0, t);
    cp_commit();

    for (int s = 0; s < 24; ++s) {
        cp_wait<0>();
        __syncthreads();

        {
            bool did = false;
            if ((s % 3) == 0 && (s / 3) + 1 < 8) { issue_A(ctx, s / 3 + 1, t); did = true; }
            if (s + 1 < 24) { issue_B(ctx, s + 1, t); did = true; }
            if (did) cp_commit();
        }

        const int chunk = s / 3;
        const int dy = (s - chunk * 3) - 1;
        const uint32_t abase = sbase + ((chunk & 1) ? A_BUF_SZ : 0u);
        const uint32_t bstage = sbase + B_OFF + (uint32_t)(s & 1) * B_STAGE;
        const int hrow_base = (warp_m + 1 + dy) * 66;

        #pragma unroll
        for (int blk_ = 0; blk_ < 6; ++blk_) {
            int blk = blk_ + phase;
            if (blk >= 6) blk -= 6;
            const int dxi = blk >> 1;
            const int k16 = blk & 1;
            const int dx = dxi - 1;
            const uint32_t btile = bstage + (uint32_t)dxi * B_TILE;

            uint32_t a[4][2][4];       // [mi][px +0 / +8][4]
            #pragma unroll
            for (int mi = 0; mi < 4; ++mi) {
                const uint32_t p = (uint32_t)(hrow_base + mi * 16 + 1 + dx + frow);
                const uint32_t pcl = (uint32_t)((k16 * 4 + fcol) ^ ((p & 1) << 2));
                const uint32_t ad = abase + p * 128 + pcl * 16;
                lds128(a[mi][0], ad);
                lds128(a[mi][1], ad + 1024);     // +8 pixels, same parity
            }
            uint32_t bb[8][4];
            #pragma unroll
            for (int nj = 0; nj < 8; ++nj) {
                const uint32_t row = (uint32_t)(warp_n * 64 + nj * 8 + frow);
                const uint32_t pcl = (uint32_t)((k16 * 4 + fcol) ^ ((row & 1) << 2));
                lds128(bb[nj], btile + row * 128 + pcl * 16);
            }
            #pragma unroll
            for (int mi = 0; mi < 4; ++mi) {
                #pragma unroll
                for (int nj = 0; nj < 8; ++nj) {
                    float* cacc = acc[mi][nj];
                    mma_tf32(cacc, a[mi][0][0], a[mi][1][0],
                                   a[mi][0][1], a[mi][1][1],
                                   bb[nj][0], bb[nj][1]);
                    mma_tf32(cacc, a[mi][0][2], a[mi][1][2],
                                   a[mi][0][3], a[mi][1][3],
                                   bb[nj][2], bb[nj][3]);
                }
            }
        }
    }

    __syncthreads();

    // ---- epilogue: transpose through smem, coalesced float4 stores ----
    float* sC = (float*)dsm;                 // [128 oc][264 px-padded]
    const int r0 = lane >> 2;
    const int col0 = (lane & 3) * 2;
    #pragma unroll
    for (int mi = 0; mi < 4; ++mi) {
        #pragma unroll
        for (int ni = 0; ni < 8; ++ni) {
            const int px = warp_m * 64 + mi * 16 + r0;
            const int oc = warp_n * 64 + ni * 8 + col0;
            sC[oc * 264 + px]           = acc[mi][ni][0];
            sC[(oc + 1) * 264 + px]     = acc[mi][ni][1];
            sC[oc * 264 + px + 8]       = acc[mi][ni][2];
            sC[(oc + 1) * 264 + px + 8] = acc[mi][ni][3];
        }
    }
    __syncthreads();

    #pragma unroll
    for (int it = 0; it < 32; ++it) {
        const int linear = t + it * 256;
        const int oc = linear >> 6;
        const int q = linear & 63;
        float4 v = *(const float4*)&sC[oc * 264 + q * 4];
        const int yy = y0 + (q >> 4);
        const int xx = (q & 15) * 4;
        *(float4*)&out[((size_t)(n * OCC + oc0 + oc) * HH + yy) * WW + xx] = v;
    }
}

// ---------------------------------------------------------------------------
extern "C" void kernel_launch(void* const* d_in, const int* in_sizes, int n_in,
                              void* d_out, int out_size) {
    const float* x  = (const float*)d_in[0];
    const float* z  = (const float*)d_in[1];
    const float* W1 = (const float*)d_in[2];
    const float* B1 = (const float*)d_in[3];
    const float* W2 = (const float*)d_in[4];
    const float* B2 = (const float*)d_in[5];
    float* out = (float*)d_out;

    x_convert_kernel<<<dim3(64, 32, 2), 256>>>(x);

    weight_gen_kernel<<<dim3(16, 16), 256>>>(z, W1, B1, W2, B2);

    cudaFuncSetAttribute(conv_mma_kernel,
                         cudaFuncAttributeMaxDynamicSharedMemorySize, SMEM_DYN);
    conv_mma_kernel<<<dim3(16, 32, 2), 256, SMEM_DYN>>>(out);
}